// round 7
// baseline (speedup 1.0000x reference)
#include <cuda_runtime.h>
#include <cstdint>

// ---------------- problem constants ----------------
#define NN     100000
#define EE     1600000
#define ET     1700000          // EE + NN self loops
#define DIM    128
#define ODIM   64
#define GDIM   512              // 4*DIM
#define KLSTM  384              // h_tmp(128) | x(128) | h(128)
#define NEG_SLOPE 0.2f
#define RESW   0.5f

// ---------------- device scratch ----------------
__device__ float g_x0[NN * DIM];
__device__ float g_x [NN * DIM];
__device__ float g_xp[NN * 3 * DIM];        // [n][l*128+d] all 3 projections
__device__ float g_ht[3 * NN * DIM];        // [l][n][d]
__device__ float g_h [NN * DIM];
__device__ float g_c [NN * DIM];
__device__ float g_agg[3 * NN * DIM];       // [l][n][d]
__device__ float g_gates[NN * GDIM];
__device__ float g_as[3 * NN];
__device__ float g_ad[3 * NN];
__device__ float g_den[3 * NN];
__device__ float g_ex[3 * ET];
__device__ float g_Wg [3 * DIM * DIM];      // gat_W transposed -> [l][n][k] == [384][128] n-major
__device__ float g_Wls[3 * GDIM * KLSTM];   // packed n-major [l][j=512][k=384]

// ---------------- weight prep ----------------
__global__ void k_prep(const float* __restrict__ gatw,
                       const float* __restrict__ wih, const float* __restrict__ whh) {
    const int WG_TOT = 3 * DIM * DIM;
    const int TOT = WG_TOT + 3 * GDIM * KLSTM;
    for (int i = blockIdx.x * blockDim.x + threadIdx.x; i < TOT; i += gridDim.x * blockDim.x) {
        if (i < WG_TOT) {
            int l = i / 16384, r = i % 16384;
            int n = r / 128, k = r % 128;
            g_Wg[i] = gatw[l * 16384 + k * 128 + n];
        } else {
            int t = i - WG_TOT;
            int l = t / (GDIM * KLSTM);
            int r = t % (GDIM * KLSTM);
            int j = r / KLSTM, k = r % KLSTM;
            g_Wls[t] = (k < 256) ? wih[l * GDIM * 256 + j * 256 + k]
                                 : whh[l * GDIM * 128 + j * 128 + (k - 256)];
        }
    }
}

__global__ void k_init_state() {
    for (int i = blockIdx.x * blockDim.x + threadIdx.x; i < NN * DIM; i += gridDim.x * blockDim.x) {
        g_h[i] = 0.f; g_c[i] = 0.f; g_x[i] = g_x0[i];
    }
}

// ---------------- tf32 tensor-core GEMM, 3-stage cp.async ring ----------------
// C[M,Nc] = A[M,K] @ B_T, B n-major [Nc][K]. BM=128, BN=128, BK=16, 256 thr,
// 8 warps 2(M)x4(N), warp tile 64x32, m16n8k8 tf32 mma, ldmatrix frags.
// ONE __syncthreads per k-iter; raw fp32 bits into tf32 mma.
// CAT=1: A gathered from A0|A1|A2 (each [M,128]).
#define BKT 16
#define TG_SMEM (6 * 128 * 20 * 4)   // 61440: sA[3][128][20] + sB[3][128][20]

__device__ __forceinline__ void cp16(uint32_t dst, const void* src, int sz) {
    asm volatile("cp.async.cg.shared.global [%0], [%1], 16, %2;\n"
                 :: "r"(dst), "l"(src), "r"(sz));
}

__device__ __forceinline__ void ldm_x4(uint32_t& r0, uint32_t& r1, uint32_t& r2, uint32_t& r3,
                                       uint32_t addr) {
    asm volatile("ldmatrix.sync.aligned.m8n8.x4.shared.b16 {%0,%1,%2,%3}, [%4];"
                 : "=r"(r0), "=r"(r1), "=r"(r2), "=r"(r3) : "r"(addr));
}

template <int CAT>
__global__ __launch_bounds__(256) void tgemm(
    const float* __restrict__ A0, const float* __restrict__ A1, const float* __restrict__ A2,
    const float* __restrict__ B, const float* __restrict__ bias, float* __restrict__ C,
    int M, int K, int Nc)
{
    extern __shared__ char smem_raw[];
    float (*sA)[128][20] = (float (*)[128][20])smem_raw;
    float (*sB)[128][20] = (float (*)[128][20])(smem_raw + 3 * 128 * 20 * 4);

    const int tid = threadIdx.x;
    const int wid = tid >> 5, lane = tid & 31;
    const int warpM = wid & 1, warpN = wid >> 1;
    const int block_row = blockIdx.y * 128;
    const int block_col = blockIdx.x * 128;
    const int grp = lane >> 2, tig = lane & 3;

    float acc[4][4][4];
#pragma unroll
    for (int mi = 0; mi < 4; mi++)
#pragma unroll
        for (int ni = 0; ni < 4; ni++)
#pragma unroll
            for (int r = 0; r < 4; r++) acc[mi][ni][r] = 0.f;

    const int nKt = K / BKT;

    auto load_stage = [&](int stage, int kt) {
        const float* Ap; int kb, astride;
        if (CAT) {
            int seg = kt >> 7;
            Ap = (seg == 0) ? A0 : (seg == 1) ? A1 : A2;
            kb = kt & 127; astride = 128;
        } else { Ap = A0; kb = kt; astride = K; }
#pragma unroll
        for (int p = 0; p < 2; p++) {
            int i = tid + p * 256;
            int m = i >> 2, kc = i & 3;
            int gr = block_row + m;
            uint32_t dst = (uint32_t)__cvta_generic_to_shared(&sA[stage][m][kc * 4]);
            cp16(dst, Ap + (size_t)gr * astride + kb + kc * 4, gr < M ? 16 : 0);
        }
#pragma unroll
        for (int p = 0; p < 2; p++) {
            int i = tid + p * 256;
            int n = i >> 2, kc = i & 3;
            int gn = block_col + n;
            uint32_t dst = (uint32_t)__cvta_generic_to_shared(&sB[stage][n][kc * 4]);
            cp16(dst, B + (size_t)gn * K + kt + kc * 4, gn < Nc ? 16 : 0);
        }
        asm volatile("cp.async.commit_group;\n");
    };

    load_stage(0, 0);
    load_stage(1, BKT);

    const int aRow = warpM * 64 + (lane & 15);
    const int aKof = (lane >> 4) << 2;
    const int bRow = warpN * 32 + ((lane >> 4) << 3) + (lane & 7);
    const int bKof = ((lane >> 3) & 1) << 2;

    int s = 0;
    for (int it = 0; it < nKt; it++) {
        asm volatile("cp.async.wait_group 1;\n");
        __syncthreads();
        // prefetch stage it+2 (its buffer was computed at it-1; sync above makes it safe)
        if (it + 2 < nKt) {
            int ns = s + 2; if (ns >= 3) ns -= 3;
            load_stage(ns, (it + 2) * BKT);
        } else {
            asm volatile("cp.async.commit_group;\n");   // keep group counting uniform
        }

        const uint32_t aBase = (uint32_t)__cvta_generic_to_shared(&sA[s][0][0]);
        const uint32_t bBase = (uint32_t)__cvta_generic_to_shared(&sB[s][0][0]);
#pragma unroll
        for (int kk = 0; kk < BKT; kk += 8) {
            uint32_t af[4][4];
#pragma unroll
            for (int mi = 0; mi < 4; mi++) {
                uint32_t addr = aBase + (uint32_t)(((aRow + mi * 16) * 20 + kk + aKof) * 4);
                ldm_x4(af[mi][0], af[mi][1], af[mi][2], af[mi][3], addr);
            }
            uint32_t bf[4][2];
#pragma unroll
            for (int nh = 0; nh < 2; nh++) {
                uint32_t addr = bBase + (uint32_t)(((bRow + nh * 16) * 20 + kk + bKof) * 4);
                uint32_t r0, r1, r2, r3;
                ldm_x4(r0, r1, r2, r3, addr);
                bf[nh * 2][0] = r0; bf[nh * 2][1] = r1;
                bf[nh * 2 + 1][0] = r2; bf[nh * 2 + 1][1] = r3;
            }
#pragma unroll
            for (int mi = 0; mi < 4; mi++)
#pragma unroll
                for (int ni = 0; ni < 4; ni++) {
                    asm volatile(
                        "mma.sync.aligned.m16n8k8.row.col.f32.tf32.tf32.f32 "
                        "{%0,%1,%2,%3}, {%4,%5,%6,%7}, {%8,%9}, {%0,%1,%2,%3};"
                        : "+f"(acc[mi][ni][0]), "+f"(acc[mi][ni][1]),
                          "+f"(acc[mi][ni][2]), "+f"(acc[mi][ni][3])
                        : "r"(af[mi][0]), "r"(af[mi][1]), "r"(af[mi][2]), "r"(af[mi][3]),
                          "r"(bf[ni][0]), "r"(bf[ni][1]));
                }
        }
        if (++s >= 3) s -= 3;
    }

#pragma unroll
    for (int mi = 0; mi < 4; mi++) {
#pragma unroll
        for (int ni = 0; ni < 4; ni++) {
            int gr0 = block_row + warpM * 64 + mi * 16 + grp;
            int gc  = block_col + warpN * 32 + ni * 8 + 2 * tig;
            if (gc >= Nc) continue;
            float b0 = 0.f, b1 = 0.f;
            if (bias) { b0 = bias[gc]; b1 = bias[gc + 1]; }
            if (gr0 < M) {
                float2 v = make_float2(acc[mi][ni][0] + b0, acc[mi][ni][1] + b1);
                *(float2*)(C + (size_t)gr0 * Nc + gc) = v;
            }
            int gr1 = gr0 + 8;
            if (gr1 < M) {
                float2 v = make_float2(acc[mi][ni][2] + b0, acc[mi][ni][3] + b1);
                *(float2*)(C + (size_t)gr1 * Nc + gc) = v;
            }
        }
    }
}

// ---------------- attention prologue: all 3 layers at once ----------------
// warp per node: 6 dot products, zero agg[3 layers] row + den.
__global__ void k_alpha3(const float* __restrict__ att_s, const float* __restrict__ att_d) {
    int node = (blockIdx.x * blockDim.x + threadIdx.x) >> 5;
    int lane = threadIdx.x & 31;
    if (node >= NN) return;
    float s1[3], s2[3];
#pragma unroll
    for (int l = 0; l < 3; l++) {
        float4 v = *(const float4*)(g_xp + (size_t)node * 384 + l * 128 + lane * 4);
        float4 a = *(const float4*)(att_s + l * 128 + lane * 4);
        float4 b = *(const float4*)(att_d + l * 128 + lane * 4);
        s1[l] = v.x * a.x + v.y * a.y + v.z * a.z + v.w * a.w;
        s2[l] = v.x * b.x + v.y * b.y + v.z * b.z + v.w * b.w;
        *(float4*)(g_agg + (size_t)l * NN * 128 + (size_t)node * 128 + lane * 4) =
            make_float4(0.f, 0.f, 0.f, 0.f);
    }
#pragma unroll
    for (int off = 16; off; off >>= 1)
#pragma unroll
        for (int l = 0; l < 3; l++) {
            s1[l] += __shfl_down_sync(0xffffffffu, s1[l], off);
            s2[l] += __shfl_down_sync(0xffffffffu, s2[l], off);
        }
    if (lane == 0)
#pragma unroll
        for (int l = 0; l < 3; l++) {
            g_as[l * NN + node] = s1[l];
            g_ad[l * NN + node] = s2[l];
            g_den[l * NN + node] = 0.f;
        }
}

__global__ void k_edge1_all(const int* __restrict__ eidx) {
    int t = blockIdx.x * blockDim.x + threadIdx.x;
    if (t >= 3 * ET) return;
    int l = t / ET, e = t - l * ET;
    int s, d;
    if (e < EE) { s = eidx[e]; d = eidx[EE + e]; }
    else        { s = d = e - EE; }
    float v = g_as[l * NN + s] + g_ad[l * NN + d];
    v = v >= 0.f ? v : NEG_SLOPE * v;
    float ex = expf(v);                        // softmax shift-invariant; |v| small
    g_ex[t] = ex;
    atomicAdd(&g_den[l * NN + d], ex);
}

__global__ void k_edge2_all(const int* __restrict__ eidx) {
    long long w = ((long long)blockIdx.x * blockDim.x + threadIdx.x) >> 5;
    if (w >= 3LL * ET) return;
    int lane = threadIdx.x & 31;
    int l = (int)(w / ET), e = (int)(w - (long long)l * ET);
    int s, d;
    if (e < EE) { s = eidx[e]; d = eidx[EE + e]; }
    else        { s = d = e - EE; }
    float wgt = g_ex[l * ET + e] / (g_den[l * NN + d] + 1e-16f);
    float4 v = *(const float4*)(g_xp + (size_t)s * 384 + l * 128 + lane * 4);
    v.x *= wgt; v.y *= wgt; v.z *= wgt; v.w *= wgt;
    atomicAdd((float4*)(g_agg + (size_t)l * NN * 128 + (size_t)d * 128 + lane * 4), v);
}

__global__ void k_tanh3(const float* __restrict__ gat_b) {
    for (long long i = (long long)blockIdx.x * blockDim.x + threadIdx.x;
         i < 3LL * NN * DIM; i += (long long)gridDim.x * blockDim.x) {
        int l = (int)(i / (NN * DIM));
        g_ht[i] = tanhf(g_agg[i] + gat_b[l * 128 + ((int)i & 127)]);
    }
}

// ---------------- LSTM elementwise ----------------
__device__ __forceinline__ float sigf(float x) { return 1.f / (1.f + expf(-x)); }

__global__ void k_lstm() {
    int i = blockIdx.x * blockDim.x + threadIdx.x;
    if (i >= NN * DIM) return;
    int n = i >> 7, j = i & 127;
    size_t base = (size_t)n * GDIM + j;
    float ii = g_gates[base];
    float ff = g_gates[base + 128];
    float gg = g_gates[base + 256];
    float oo = g_gates[base + 384];
    float c = g_c[i];
    c = sigf(ff) * c + sigf(ii) * tanhf(gg);
    float h = sigf(oo) * tanhf(c);
    g_c[i] = c;
    g_h[i] = h;
    g_x[i] = h + RESW * g_x0[i];
}

// ---------------- final log_softmax ----------------
__global__ void k_logsoftmax(float* __restrict__ out) {
    int warp = (blockIdx.x * blockDim.x + threadIdx.x) >> 5;
    int lane = threadIdx.x & 31;
    if (warp >= NN) return;
    float* row = out + (size_t)warp * ODIM;
    float v0 = row[lane], v1 = row[lane + 32];
    float m = fmaxf(v0, v1);
#pragma unroll
    for (int off = 16; off; off >>= 1) m = fmaxf(m, __shfl_xor_sync(0xffffffffu, m, off));
    float s = expf(v0 - m) + expf(v1 - m);
#pragma unroll
    for (int off = 16; off; off >>= 1) s += __shfl_xor_sync(0xffffffffu, s, off);
    float l = m + logf(s);
    row[lane] = v0 - l;
    row[lane + 32] = v1 - l;
}

// ---------------- launch ----------------
extern "C" void kernel_launch(void* const* d_in, const int* in_sizes, int n_in,
                              void* d_out, int out_size) {
    const float* x_in    = (const float*)d_in[0];
    const int*   eidx    = (const int*)  d_in[1];
    const float* lin1_w  = (const float*)d_in[2];   // n-major, direct B
    const float* lin1_b  = (const float*)d_in[3];
    const float* gat_W   = (const float*)d_in[4];
    const float* att_src = (const float*)d_in[5];
    const float* att_dst = (const float*)d_in[6];
    const float* gat_b   = (const float*)d_in[7];
    const float* lstmWih = (const float*)d_in[8];
    const float* lstmWhh = (const float*)d_in[9];
    const float* lin2_w  = (const float*)d_in[10];  // n-major, direct B
    const float* lin2_b  = (const float*)d_in[11];
    float* out = (float*)d_out;

    float *p_x0, *p_x, *p_xp, *p_ht, *p_h, *p_gates, *p_Wg, *p_Wls;
    cudaGetSymbolAddress((void**)&p_x0,    g_x0);
    cudaGetSymbolAddress((void**)&p_x,     g_x);
    cudaGetSymbolAddress((void**)&p_xp,    g_xp);
    cudaGetSymbolAddress((void**)&p_ht,    g_ht);
    cudaGetSymbolAddress((void**)&p_h,     g_h);
    cudaGetSymbolAddress((void**)&p_gates, g_gates);
    cudaGetSymbolAddress((void**)&p_Wg,    g_Wg);
    cudaGetSymbolAddress((void**)&p_Wls,   g_Wls);

    cudaFuncSetAttribute(tgemm<0>, cudaFuncAttributeMaxDynamicSharedMemorySize, TG_SMEM);
    cudaFuncSetAttribute(tgemm<1>, cudaFuncAttributeMaxDynamicSharedMemorySize, TG_SMEM);

    const int T = 256;
    const int rowBlocks = (NN + 127) / 128;   // 782

    k_prep<<<1200, T>>>(gat_W, lstmWih, lstmWhh);

    // lin1
    tgemm<0><<<dim3(1, rowBlocks), T, TG_SMEM>>>(x_in, nullptr, nullptr, lin1_w, lin1_b, p_x0, NN, 128, 128);
    k_init_state<<<2048, T>>>();

    // all 3 GAT projections in one GEMM: xp_all = x0 @ [Wg0|Wg1|Wg2]
    tgemm<0><<<dim3(3, rowBlocks), T, TG_SMEM>>>(p_x0, nullptr, nullptr, p_Wg, nullptr, p_xp, NN, 128, 384);

    // batched attention for all layers
    k_alpha3<<<(NN * 32 + T - 1) / T, T>>>(att_src, att_dst);
    k_edge1_all<<<(3 * ET + T - 1) / T, T>>>(eidx);
    {
        long long th = 3LL * ET * 32;
        k_edge2_all<<<(unsigned)((th + T - 1) / T), T>>>(eidx);
    }
    k_tanh3<<<4096, T>>>(gat_b);

    // sequential LSTM layers
    for (int l = 0; l < 3; l++) {
        tgemm<1><<<dim3(4, rowBlocks), T, TG_SMEM>>>(p_ht + (size_t)l * NN * DIM, p_x, p_h,
                                                     p_Wls + (size_t)l * GDIM * KLSTM, nullptr, p_gates,
                                                     NN, KLSTM, GDIM);
        k_lstm<<<(NN * DIM + T - 1) / T, T>>>();
    }

    tgemm<0><<<dim3(1, rowBlocks), T, TG_SMEM>>>(p_x, nullptr, nullptr, lin2_w, lin2_b, out, NN, 128, ODIM);
    k_logsoftmax<<<(NN * 32 + T - 1) / T, T>>>(out);
}

// round 8
// speedup vs baseline: 1.4153x; 1.4153x over previous
#include <cuda_runtime.h>
#include <cstdint>

// ---------------- problem constants ----------------
#define NN     100000
#define EE     1600000
#define ET     1700000          // EE + NN self loops
#define DIM    128
#define ODIM   64
#define GDIM   512              // 4*DIM
#define KLSTM  384              // h_tmp(128) | x(128) | h(128)
#define NEG_SLOPE 0.2f
#define RESW   0.5f

// ---------------- device scratch ----------------
__device__ float g_x0[NN * DIM];
__device__ float g_x [NN * DIM];
__device__ float g_xp[NN * 3 * DIM];        // [n][l*128+d]
__device__ float g_ht[NN * DIM];            // per-layer (reused)
__device__ float g_h [NN * DIM];
__device__ float g_c [NN * DIM];
__device__ float g_gates[NN * GDIM];
__device__ float g_as[3 * NN];
__device__ float g_ad[3 * NN];
__device__ int   g_cnt[NN];
__device__ int   g_cur[NN];
__device__ int   g_off[NN + 1];
__device__ int   g_srcl[ET];                // CSR: src ids grouped by dst
__device__ float g_Wg [3 * DIM * DIM];      // gat_W transposed: [384][128] n-major
__device__ float g_Wls[3 * GDIM * KLSTM];   // packed n-major [l][512][384]

// ---------------- weight prep ----------------
__global__ void k_prep(const float* __restrict__ gatw,
                       const float* __restrict__ wih, const float* __restrict__ whh) {
    const int WG_TOT = 3 * DIM * DIM;
    const int TOT = WG_TOT + 3 * GDIM * KLSTM;
    for (int i = blockIdx.x * blockDim.x + threadIdx.x; i < TOT; i += gridDim.x * blockDim.x) {
        if (i < WG_TOT) {
            int l = i / 16384, r = i % 16384;
            int n = r / 128, k = r % 128;
            g_Wg[i] = gatw[l * 16384 + k * 128 + n];
        } else {
            int t = i - WG_TOT;
            int l = t / (GDIM * KLSTM);
            int r = t % (GDIM * KLSTM);
            int j = r / KLSTM, k = r % KLSTM;
            g_Wls[t] = (k < 256) ? wih[l * GDIM * 256 + j * 256 + k]
                                 : whh[l * GDIM * 128 + j * 128 + (k - 256)];
        }
    }
}

__global__ void k_init_state() {
    for (int i = blockIdx.x * blockDim.x + threadIdx.x; i < NN * DIM; i += gridDim.x * blockDim.x) {
        g_h[i] = 0.f; g_c[i] = 0.f; g_x[i] = g_x0[i];
    }
}

// ---------------- CSR build (one-time) ----------------
__global__ void k_zero_cnt() {
    for (int i = blockIdx.x * blockDim.x + threadIdx.x; i < NN; i += gridDim.x * blockDim.x) {
        g_cnt[i] = 0; g_cur[i] = 0;
    }
}

__global__ void k_hist(const int* __restrict__ eidx) {
    int e = blockIdx.x * blockDim.x + threadIdx.x;
    if (e >= ET) return;
    int d = (e < EE) ? eidx[EE + e] : e - EE;
    atomicAdd(&g_cnt[d], 1);
}

__global__ void k_scan() {     // single block, 1024 threads
    __shared__ int wsum[32];
    __shared__ int carry;
    int tid = threadIdx.x, lane = tid & 31, wid = tid >> 5;
    if (tid == 0) { carry = 0; g_off[0] = 0; }
    __syncthreads();
    for (int base = 0; base < NN; base += 1024) {
        int i = base + tid;
        int v = (i < NN) ? g_cnt[i] : 0;
        int x = v;
#pragma unroll
        for (int off = 1; off < 32; off <<= 1) {
            int t = __shfl_up_sync(0xffffffffu, x, off);
            if (lane >= off) x += t;
        }
        if (lane == 31) wsum[wid] = x;
        __syncthreads();
        if (wid == 0) {
            int y = wsum[lane];
#pragma unroll
            for (int off = 1; off < 32; off <<= 1) {
                int t = __shfl_up_sync(0xffffffffu, y, off);
                if (lane >= off) y += t;
            }
            wsum[lane] = y;
        }
        __syncthreads();
        int incl = x + (wid > 0 ? wsum[wid - 1] : 0) + carry;
        if (i < NN) g_off[i + 1] = incl;
        __syncthreads();
        if (tid == 1023) carry = incl;
        __syncthreads();
    }
}

__global__ void k_scatter(const int* __restrict__ eidx) {
    int e = blockIdx.x * blockDim.x + threadIdx.x;
    if (e >= ET) return;
    int s, d;
    if (e < EE) { s = eidx[e]; d = eidx[EE + e]; }
    else        { s = d = e - EE; }
    int pos = g_off[d] + atomicAdd(&g_cur[d], 1);
    g_srcl[pos] = s;
}

// ---------------- tf32 tensor-core GEMM, 3-stage cp.async ring ----------------
#define BKT 16
#define TG_SMEM (6 * 128 * 20 * 4)   // 61440

__device__ __forceinline__ void cp16(uint32_t dst, const void* src, int sz) {
    asm volatile("cp.async.cg.shared.global [%0], [%1], 16, %2;\n"
                 :: "r"(dst), "l"(src), "r"(sz));
}

__device__ __forceinline__ void ldm_x4(uint32_t& r0, uint32_t& r1, uint32_t& r2, uint32_t& r3,
                                       uint32_t addr) {
    asm volatile("ldmatrix.sync.aligned.m8n8.x4.shared.b16 {%0,%1,%2,%3}, [%4];"
                 : "=r"(r0), "=r"(r1), "=r"(r2), "=r"(r3) : "r"(addr));
}

template <int CAT>
__global__ __launch_bounds__(256) void tgemm(
    const float* __restrict__ A0, const float* __restrict__ A1, const float* __restrict__ A2,
    const float* __restrict__ B, const float* __restrict__ bias, float* __restrict__ C,
    int M, int K, int Nc)
{
    extern __shared__ char smem_raw[];
    float (*sA)[128][20] = (float (*)[128][20])smem_raw;
    float (*sB)[128][20] = (float (*)[128][20])(smem_raw + 3 * 128 * 20 * 4);

    const int tid = threadIdx.x;
    const int wid = tid >> 5, lane = tid & 31;
    const int warpM = wid & 1, warpN = wid >> 1;
    const int block_row = blockIdx.y * 128;
    const int block_col = blockIdx.x * 128;
    const int grp = lane >> 2, tig = lane & 3;

    float acc[4][4][4];
#pragma unroll
    for (int mi = 0; mi < 4; mi++)
#pragma unroll
        for (int ni = 0; ni < 4; ni++)
#pragma unroll
            for (int r = 0; r < 4; r++) acc[mi][ni][r] = 0.f;

    const int nKt = K / BKT;

    auto load_stage = [&](int stage, int kt) {
        const float* Ap; int kb, astride;
        if (CAT) {
            int seg = kt >> 7;
            Ap = (seg == 0) ? A0 : (seg == 1) ? A1 : A2;
            kb = kt & 127; astride = 128;
        } else { Ap = A0; kb = kt; astride = K; }
#pragma unroll
        for (int p = 0; p < 2; p++) {
            int i = tid + p * 256;
            int m = i >> 2, kc = i & 3;
            int gr = block_row + m;
            uint32_t dst = (uint32_t)__cvta_generic_to_shared(&sA[stage][m][kc * 4]);
            cp16(dst, Ap + (size_t)gr * astride + kb + kc * 4, gr < M ? 16 : 0);
        }
#pragma unroll
        for (int p = 0; p < 2; p++) {
            int i = tid + p * 256;
            int n = i >> 2, kc = i & 3;
            int gn = block_col + n;
            uint32_t dst = (uint32_t)__cvta_generic_to_shared(&sB[stage][n][kc * 4]);
            cp16(dst, B + (size_t)gn * K + kt + kc * 4, gn < Nc ? 16 : 0);
        }
        asm volatile("cp.async.commit_group;\n");
    };

    load_stage(0, 0);
    load_stage(1, BKT);

    const int aRow = warpM * 64 + (lane & 15);
    const int aKof = (lane >> 4) << 2;
    const int bRow = warpN * 32 + ((lane >> 4) << 3) + (lane & 7);
    const int bKof = ((lane >> 3) & 1) << 2;

    int s = 0;
    for (int it = 0; it < nKt; it++) {
        asm volatile("cp.async.wait_group 1;\n");
        __syncthreads();
        if (it + 2 < nKt) {
            int ns = s + 2; if (ns >= 3) ns -= 3;
            load_stage(ns, (it + 2) * BKT);
        } else {
            asm volatile("cp.async.commit_group;\n");
        }

        const uint32_t aBase = (uint32_t)__cvta_generic_to_shared(&sA[s][0][0]);
        const uint32_t bBase = (uint32_t)__cvta_generic_to_shared(&sB[s][0][0]);
#pragma unroll
        for (int kk = 0; kk < BKT; kk += 8) {
            uint32_t af[4][4];
#pragma unroll
            for (int mi = 0; mi < 4; mi++) {
                uint32_t addr = aBase + (uint32_t)(((aRow + mi * 16) * 20 + kk + aKof) * 4);
                ldm_x4(af[mi][0], af[mi][1], af[mi][2], af[mi][3], addr);
            }
            uint32_t bf[4][2];
#pragma unroll
            for (int nh = 0; nh < 2; nh++) {
                uint32_t addr = bBase + (uint32_t)(((bRow + nh * 16) * 20 + kk + bKof) * 4);
                uint32_t r0, r1, r2, r3;
                ldm_x4(r0, r1, r2, r3, addr);
                bf[nh * 2][0] = r0; bf[nh * 2][1] = r1;
                bf[nh * 2 + 1][0] = r2; bf[nh * 2 + 1][1] = r3;
            }
#pragma unroll
            for (int mi = 0; mi < 4; mi++)
#pragma unroll
                for (int ni = 0; ni < 4; ni++) {
                    asm volatile(
                        "mma.sync.aligned.m16n8k8.row.col.f32.tf32.tf32.f32 "
                        "{%0,%1,%2,%3}, {%4,%5,%6,%7}, {%8,%9}, {%0,%1,%2,%3};"
                        : "+f"(acc[mi][ni][0]), "+f"(acc[mi][ni][1]),
                          "+f"(acc[mi][ni][2]), "+f"(acc[mi][ni][3])
                        : "r"(af[mi][0]), "r"(af[mi][1]), "r"(af[mi][2]), "r"(af[mi][3]),
                          "r"(bf[ni][0]), "r"(bf[ni][1]));
                }
        }
        if (++s >= 3) s -= 3;
    }

#pragma unroll
    for (int mi = 0; mi < 4; mi++) {
#pragma unroll
        for (int ni = 0; ni < 4; ni++) {
            int gr0 = block_row + warpM * 64 + mi * 16 + grp;
            int gc  = block_col + warpN * 32 + ni * 8 + 2 * tig;
            if (gc >= Nc) continue;
            float b0 = 0.f, b1 = 0.f;
            if (bias) { b0 = bias[gc]; b1 = bias[gc + 1]; }
            if (gr0 < M) {
                float2 v = make_float2(acc[mi][ni][0] + b0, acc[mi][ni][1] + b1);
                *(float2*)(C + (size_t)gr0 * Nc + gc) = v;
            }
            int gr1 = gr0 + 8;
            if (gr1 < M) {
                float2 v = make_float2(acc[mi][ni][2] + b0, acc[mi][ni][3] + b1);
                *(float2*)(C + (size_t)gr1 * Nc + gc) = v;
            }
        }
    }
}

// ---------------- attention coefficients for all 3 layers ----------------
__global__ void k_alpha3(const float* __restrict__ att_s, const float* __restrict__ att_d) {
    int node = (blockIdx.x * blockDim.x + threadIdx.x) >> 5;
    int lane = threadIdx.x & 31;
    if (node >= NN) return;
    float s1[3], s2[3];
#pragma unroll
    for (int l = 0; l < 3; l++) {
        float4 v = *(const float4*)(g_xp + (size_t)node * 384 + l * 128 + lane * 4);
        float4 a = *(const float4*)(att_s + l * 128 + lane * 4);
        float4 b = *(const float4*)(att_d + l * 128 + lane * 4);
        s1[l] = v.x * a.x + v.y * a.y + v.z * a.z + v.w * a.w;
        s2[l] = v.x * b.x + v.y * b.y + v.z * b.z + v.w * b.w;
    }
#pragma unroll
    for (int off = 16; off; off >>= 1)
#pragma unroll
        for (int l = 0; l < 3; l++) {
            s1[l] += __shfl_down_sync(0xffffffffu, s1[l], off);
            s2[l] += __shfl_down_sync(0xffffffffu, s2[l], off);
        }
    if (lane == 0)
#pragma unroll
        for (int l = 0; l < 3; l++) {
            g_as[l * NN + node] = s1[l];
            g_ad[l * NN + node] = s2[l];
        }
}

// ---------------- fused GAT aggregation (CSR, atomic-free) ----------------
// warp per dst node: walk incoming edges, softmax-weight xp[src], write
// ht = tanh(agg/den + bias). No atomics, no den/ex arrays, no zeroing.
__global__ void k_gat_agg(int l, const float* __restrict__ gat_b) {
    int dst = (blockIdx.x * blockDim.x + threadIdx.x) >> 5;
    int lane = threadIdx.x & 31;
    if (dst >= NN) return;
    const int beg = g_off[dst], end = g_off[dst + 1];
    const float ad = g_ad[l * NN + dst];
    const float* asv = g_as + l * NN;
    const float* xpB = g_xp + l * 128 + lane * 4;

    float4 acc = make_float4(0.f, 0.f, 0.f, 0.f);
    float den = 0.f;
    for (int base = beg; base < end; base += 32) {
        int mysrc = (base + lane < end) ? g_srcl[base + lane] : 0;
        int n = min(32, end - base);
        for (int j = 0; j < n; j++) {
            int src = __shfl_sync(0xffffffffu, mysrc, j);
            float e = asv[src] + ad;
            e = e >= 0.f ? e : NEG_SLOPE * e;
            float w = __expf(e);                 // softmax shift-invariant; |e| small
            den += w;
            float4 v = *(const float4*)(xpB + (size_t)src * 384);
            acc.x += w * v.x; acc.y += w * v.y; acc.z += w * v.z; acc.w += w * v.w;
        }
    }
    float inv = 1.f / (den + 1e-16f);
    float4 b = *(const float4*)(gat_b + l * 128 + lane * 4);
    float4 o;
    o.x = tanhf(acc.x * inv + b.x);
    o.y = tanhf(acc.y * inv + b.y);
    o.z = tanhf(acc.z * inv + b.z);
    o.w = tanhf(acc.w * inv + b.w);
    *(float4*)(g_ht + (size_t)dst * 128 + lane * 4) = o;
}

// ---------------- LSTM elementwise ----------------
__device__ __forceinline__ float sigf(float x) { return 1.f / (1.f + __expf(-x)); }

__global__ void k_lstm() {
    int i = blockIdx.x * blockDim.x + threadIdx.x;
    if (i >= NN * DIM) return;
    int n = i >> 7, j = i & 127;
    size_t base = (size_t)n * GDIM + j;
    float ii = g_gates[base];
    float ff = g_gates[base + 128];
    float gg = g_gates[base + 256];
    float oo = g_gates[base + 384];
    float c = g_c[i];
    c = sigf(ff) * c + sigf(ii) * tanhf(gg);
    float h = sigf(oo) * tanhf(c);
    g_c[i] = c;
    g_h[i] = h;
    g_x[i] = h + RESW * g_x0[i];
}

// ---------------- final log_softmax ----------------
__global__ void k_logsoftmax(float* __restrict__ out) {
    int warp = (blockIdx.x * blockDim.x + threadIdx.x) >> 5;
    int lane = threadIdx.x & 31;
    if (warp >= NN) return;
    float* row = out + (size_t)warp * ODIM;
    float v0 = row[lane], v1 = row[lane + 32];
    float m = fmaxf(v0, v1);
#pragma unroll
    for (int off = 16; off; off >>= 1) m = fmaxf(m, __shfl_xor_sync(0xffffffffu, m, off));
    float s = __expf(v0 - m) + __expf(v1 - m);
#pragma unroll
    for (int off = 16; off; off >>= 1) s += __shfl_xor_sync(0xffffffffu, s, off);
    float l = m + logf(s);
    row[lane] = v0 - l;
    row[lane + 32] = v1 - l;
}

// ---------------- launch ----------------
extern "C" void kernel_launch(void* const* d_in, const int* in_sizes, int n_in,
                              void* d_out, int out_size) {
    const float* x_in    = (const float*)d_in[0];
    const int*   eidx    = (const int*)  d_in[1];
    const float* lin1_w  = (const float*)d_in[2];
    const float* lin1_b  = (const float*)d_in[3];
    const float* gat_W   = (const float*)d_in[4];
    const float* att_src = (const float*)d_in[5];
    const float* att_dst = (const float*)d_in[6];
    const float* gat_b   = (const float*)d_in[7];
    const float* lstmWih = (const float*)d_in[8];
    const float* lstmWhh = (const float*)d_in[9];
    const float* lin2_w  = (const float*)d_in[10];
    const float* lin2_b  = (const float*)d_in[11];
    float* out = (float*)d_out;

    float *p_x0, *p_x, *p_xp, *p_ht, *p_h, *p_gates, *p_Wg, *p_Wls;
    cudaGetSymbolAddress((void**)&p_x0,    g_x0);
    cudaGetSymbolAddress((void**)&p_x,     g_x);
    cudaGetSymbolAddress((void**)&p_xp,    g_xp);
    cudaGetSymbolAddress((void**)&p_ht,    g_ht);
    cudaGetSymbolAddress((void**)&p_h,     g_h);
    cudaGetSymbolAddress((void**)&p_gates, g_gates);
    cudaGetSymbolAddress((void**)&p_Wg,    g_Wg);
    cudaGetSymbolAddress((void**)&p_Wls,   g_Wls);

    cudaFuncSetAttribute(tgemm<0>, cudaFuncAttributeMaxDynamicSharedMemorySize, TG_SMEM);
    cudaFuncSetAttribute(tgemm<1>, cudaFuncAttributeMaxDynamicSharedMemorySize, TG_SMEM);

    const int T = 256;
    const int rowBlocks = (NN + 127) / 128;   // 782

    k_prep<<<1200, T>>>(gat_W, lstmWih, lstmWhh);

    // one-time CSR build
    k_zero_cnt<<<(NN + T - 1) / T, T>>>();
    k_hist<<<(ET + T - 1) / T, T>>>(eidx);
    k_scan<<<1, 1024>>>();
    k_scatter<<<(ET + T - 1) / T, T>>>(eidx);

    // lin1
    tgemm<0><<<dim3(1, rowBlocks), T, TG_SMEM>>>(x_in, nullptr, nullptr, lin1_w, lin1_b, p_x0, NN, 128, 128);
    k_init_state<<<2048, T>>>();

    // all 3 GAT projections in one GEMM
    tgemm<0><<<dim3(3, rowBlocks), T, TG_SMEM>>>(p_x0, nullptr, nullptr, p_Wg, nullptr, p_xp, NN, 128, 384);
    k_alpha3<<<(NN * 32 + T - 1) / T, T>>>(att_src, att_dst);

    for (int l = 0; l < 3; l++) {
        k_gat_agg<<<(NN * 32 + T - 1) / T, T>>>(l, gat_b);
        tgemm<1><<<dim3(4, rowBlocks), T, TG_SMEM>>>(p_ht, p_x, p_h,
                                                     p_Wls + (size_t)l * GDIM * KLSTM, nullptr, p_gates,
                                                     NN, KLSTM, GDIM);
        k_lstm<<<(NN * DIM + T - 1) / T, T>>>();
    }

    tgemm<0><<<dim3(1, rowBlocks), T, TG_SMEM>>>(p_x, nullptr, nullptr, lin2_w, lin2_b, out, NN, 128, ODIM);
    k_logsoftmax<<<(NN * 32 + T - 1) / T, T>>>(out);
}